// round 1
// baseline (speedup 1.0000x reference)
#include <cuda_runtime.h>
#include <math.h>

#define NN 10000
#define EE 160000
#define HH 512
#define CC 10
#define BN_EPS 1e-5f

// ---------------- device scratch (no allocations allowed) ----------------
__device__ float g_h1[NN * HH];
__device__ float g_h2[NN * HH];
__device__ float g_agg[NN * HH];
__device__ float g_scale[NN];
__device__ int   g_degi[NN];
__device__ int   g_rowptr[NN + 1];
__device__ int   g_fill[NN];
__device__ int   g_esrc[EE];
__device__ float g_sum[HH];
__device__ float g_sq[HH];
__device__ float g_bnA[HH];
__device__ float g_bnB[HH];

// ---------------- CSR build ----------------
__global__ void k_zerocsr() {
    int i = blockIdx.x * blockDim.x + threadIdx.x;
    if (i < NN) { g_degi[i] = 0; g_fill[i] = 0; }
}

__global__ void k_deg(const int* __restrict__ ei) {
    int e = blockIdx.x * blockDim.x + threadIdx.x;
    if (e < EE) atomicAdd(&g_degi[ei[EE + e]], 1);
}

// single-block exclusive scan of g_degi -> g_rowptr (N=10000, chunks of 1024)
__global__ void k_scan() {
    __shared__ int sh[1024];
    __shared__ int carry;
    int t = threadIdx.x;
    if (t == 0) carry = 0;
    __syncthreads();
    for (int base = 0; base < NN; base += 1024) {
        int i = base + t;
        int v = (i < NN) ? g_degi[i] : 0;
        sh[t] = v;
        __syncthreads();
        for (int off = 1; off < 1024; off <<= 1) {
            int tv = (t >= off) ? sh[t - off] : 0;
            __syncthreads();
            sh[t] += tv;
            __syncthreads();
        }
        if (i < NN) g_rowptr[i + 1] = carry + sh[t];
        __syncthreads();
        if (t == 0) carry += sh[1023];
        __syncthreads();
    }
    if (t == 0) g_rowptr[0] = 0;
}

__global__ void k_scale() {
    int i = blockIdx.x * blockDim.x + threadIdx.x;
    if (i < NN) {
        int d = g_degi[i];
        g_scale[i] = 1.0f / (float)(d > 0 ? d : 1);
    }
}

__global__ void k_fill(const int* __restrict__ ei) {
    int e = blockIdx.x * blockDim.x + threadIdx.x;
    if (e < EE) {
        int dst = ei[EE + e];
        int pos = g_rowptr[dst] + atomicAdd(&g_fill[dst], 1);
        g_esrc[pos] = ei[e];
    }
}

// ---------------- mean aggregation (block per node, 128 thr, float4) ----------------
__global__ void k_agg(const float* __restrict__ h, float* __restrict__ out) {
    int node = blockIdx.x;
    int t = threadIdx.x;                 // 0..127 -> 4 floats each
    int s = g_rowptr[node];
    int e = g_rowptr[node + 1];
    float ax = 0.f, ay = 0.f, az = 0.f, aw = 0.f;
    int j = s;
    for (; j + 1 < e; j += 2) {
        int s0 = g_esrc[j];
        int s1 = g_esrc[j + 1];
        float4 v0 = ((const float4*)(h + (size_t)s0 * HH))[t];
        float4 v1 = ((const float4*)(h + (size_t)s1 * HH))[t];
        ax += v0.x + v1.x; ay += v0.y + v1.y;
        az += v0.z + v1.z; aw += v0.w + v1.w;
    }
    if (j < e) {
        int s0 = g_esrc[j];
        float4 v0 = ((const float4*)(h + (size_t)s0 * HH))[t];
        ax += v0.x; ay += v0.y; az += v0.z; aw += v0.w;
    }
    float sc = g_scale[node];
    ((float4*)(out + (size_t)node * HH))[t] = make_float4(ax * sc, ay * sc, az * sc, aw * sc);
}

// ---------------- dual GEMM: C = A1 @ W1^T + A2 @ W2^T (+relu) ----------------
// A1,A2: (NN,HH) row-major. W1,W2: (HH,HH) row-major (out_c, in_c). C: (NN,HH).
#define BM 64
#define BNT 64
#define BK 16

__global__ __launch_bounds__(256)
void k_gemm_dual(const float* __restrict__ A1, const float* __restrict__ A2,
                 const float* __restrict__ W1, const float* __restrict__ W2,
                 float* __restrict__ Cmat, int relu) {
    __shared__ float As[BK][BM];
    __shared__ float Bs[BK][BNT];
    int tx = threadIdx.x;                // 0..255
    int m0 = blockIdx.y * BM;
    int n0 = blockIdx.x * BNT;
    int tm = tx >> 4;                    // 0..15
    int tn = tx & 15;                    // 0..15
    int arow = tx >> 2;                  // 0..63
    int akq  = (tx & 3) * 4;             // 0,4,8,12

    float acc[4][4];
#pragma unroll
    for (int i = 0; i < 4; i++)
#pragma unroll
        for (int jj = 0; jj < 4; jj++) acc[i][jj] = 0.f;

    const int NKT = (2 * HH) / BK;       // 64
    for (int kt = 0; kt < NKT; ++kt) {
        const float* A; const float* W; int k0;
        if (kt < HH / BK) { A = A1; W = W1; k0 = kt * BK; }
        else              { A = A2; W = W2; k0 = (kt - HH / BK) * BK; }

        int gm = m0 + arow;
        float4 av = make_float4(0.f, 0.f, 0.f, 0.f);
        if (gm < NN) av = *(const float4*)(A + (size_t)gm * HH + k0 + akq);
        float4 bv = *(const float4*)(W + (size_t)(n0 + arow) * HH + k0 + akq);

        __syncthreads();
        As[akq + 0][arow] = av.x; As[akq + 1][arow] = av.y;
        As[akq + 2][arow] = av.z; As[akq + 3][arow] = av.w;
        Bs[akq + 0][arow] = bv.x; Bs[akq + 1][arow] = bv.y;
        Bs[akq + 2][arow] = bv.z; Bs[akq + 3][arow] = bv.w;
        __syncthreads();

#pragma unroll
        for (int kk = 0; kk < BK; ++kk) {
            float4 a = *(const float4*)&As[kk][tm * 4];
            float4 b = *(const float4*)&Bs[kk][tn * 4];
            acc[0][0] += a.x * b.x; acc[0][1] += a.x * b.y; acc[0][2] += a.x * b.z; acc[0][3] += a.x * b.w;
            acc[1][0] += a.y * b.x; acc[1][1] += a.y * b.y; acc[1][2] += a.y * b.z; acc[1][3] += a.y * b.w;
            acc[2][0] += a.z * b.x; acc[2][1] += a.z * b.y; acc[2][2] += a.z * b.z; acc[2][3] += a.z * b.w;
            acc[3][0] += a.w * b.x; acc[3][1] += a.w * b.y; acc[3][2] += a.w * b.z; acc[3][3] += a.w * b.w;
        }
    }

#pragma unroll
    for (int i = 0; i < 4; i++) {
        int gm = m0 + tm * 4 + i;
        if (gm < NN) {
            float4 r = make_float4(acc[i][0], acc[i][1], acc[i][2], acc[i][3]);
            if (relu) {
                r.x = fmaxf(r.x, 0.f); r.y = fmaxf(r.y, 0.f);
                r.z = fmaxf(r.z, 0.f); r.w = fmaxf(r.w, 0.f);
            }
            *(float4*)(Cmat + (size_t)gm * HH + n0 + tn * 4) = r;
        }
    }
}

// ---------------- BatchNorm ----------------
__global__ void k_zerostats() {
    int f = threadIdx.x;
    g_sum[f] = 0.f; g_sq[f] = 0.f;
}

__global__ void k_bnstats(const float* __restrict__ h) {
    int f = blockIdx.x * 128 + threadIdx.x;      // grid.x = 4
    int r0 = blockIdx.y * 157;                   // grid.y = 64 -> covers 10048
    int r1 = r0 + 157; if (r1 > NN) r1 = NN;
    float s = 0.f, q = 0.f;
    for (int r = r0; r < r1; ++r) {
        float v = h[(size_t)r * HH + f];
        s += v; q += v * v;
    }
    atomicAdd(&g_sum[f], s);
    atomicAdd(&g_sq[f], q);
}

__global__ void k_bnfin(const float* __restrict__ gamma, const float* __restrict__ beta) {
    int f = threadIdx.x;
    float mu = g_sum[f] / (float)NN;
    float var = g_sq[f] / (float)NN - mu * mu;
    float inv = rsqrtf(var + BN_EPS);
    float sc = gamma[f] * inv;
    g_bnA[f] = sc;
    g_bnB[f] = beta[f] - mu * sc;
}

__global__ void k_bnapply(float* __restrict__ h) {
    int idx = blockIdx.x * blockDim.x + threadIdx.x;   // over NN*HH/4
    if (idx >= NN * HH / 4) return;
    int f4 = idx & (HH / 4 - 1);
    float4 v = ((float4*)h)[idx];
    float4 a = ((const float4*)g_bnA)[f4];
    float4 b = ((const float4*)g_bnB)[f4];
    v.x = v.x * a.x + b.x;
    v.y = v.y * a.y + b.y;
    v.z = v.z * a.z + b.z;
    v.w = v.w * a.w + b.w;
    ((float4*)h)[idx] = v;
}

// ---------------- final conv (C=10) + log_softmax ----------------
__global__ __launch_bounds__(320)
void k_final(const float* __restrict__ agg, const float* __restrict__ h,
             const float* __restrict__ Wr, const float* __restrict__ Ww,
             float* __restrict__ out) {
    __shared__ float sa[HH];
    __shared__ float sh[HH];
    __shared__ float slog[CC];
    __shared__ float sLse;
    int node = blockIdx.x;
    int t = threadIdx.x;                 // 320 = 10 warps
    for (int i = t; i < HH; i += 320) {
        sa[i] = agg[(size_t)node * HH + i];
        sh[i] = h[(size_t)node * HH + i];
    }
    __syncthreads();
    int w = t >> 5, lane = t & 31;
    float s = 0.f;
    for (int k = lane; k < HH; k += 32)
        s += sa[k] * Wr[w * HH + k] + sh[k] * Ww[w * HH + k];
#pragma unroll
    for (int o = 16; o; o >>= 1) s += __shfl_down_sync(0xffffffff, s, o);
    if (lane == 0) slog[w] = s;
    __syncthreads();
    if (t == 0) {
        float mx = slog[0];
        for (int c = 1; c < CC; c++) mx = fmaxf(mx, slog[c]);
        float sum = 0.f;
        for (int c = 0; c < CC; c++) sum += expf(slog[c] - mx);
        sLse = mx + logf(sum);
    }
    __syncthreads();
    if (t < CC) out[(size_t)node * CC + t] = slog[t] - sLse;
}

// ---------------- launch ----------------
extern "C" void kernel_launch(void* const* d_in, const int* in_sizes, int n_in,
                              void* d_out, int out_size) {
    const float* x        = (const float*)d_in[0];
    const int*   ei       = (const int*)d_in[1];
    const float* Wpr      = (const float*)d_in[2];
    const float* Wpw      = (const float*)d_in[3];
    const float* Wrel     = (const float*)d_in[4];   // (3,512,512)
    const float* Wroot    = (const float*)d_in[5];
    const float* gamma    = (const float*)d_in[6];   // (4,512)
    const float* beta     = (const float*)d_in[7];
    const float* Wfr      = (const float*)d_in[8];   // (10,512)
    const float* Wfw      = (const float*)d_in[9];
    float* out = (float*)d_out;

    // resolve device-global addresses once
    static float *p_h1 = nullptr, *p_h2 = nullptr, *p_agg = nullptr;
    if (!p_h1) {
        cudaGetSymbolAddress((void**)&p_h1, g_h1);
        cudaGetSymbolAddress((void**)&p_h2, g_h2);
        cudaGetSymbolAddress((void**)&p_agg, g_agg);
    }

    dim3 gemmGrid(HH / BNT, (NN + BM - 1) / BM);   // (8, 157)
    int eb = (EE + 255) / 256;
    int nb = (NN + 255) / 256;
    int apb = (NN * HH / 4 + 255) / 256;

    // CSR build
    k_zerocsr<<<nb, 256>>>();
    k_deg<<<eb, 256>>>(ei);
    k_scan<<<1, 1024>>>();
    k_scale<<<nb, 256>>>();
    k_fill<<<eb, 256>>>(ei);

    // proj layer: conv(x) -> relu -> bn   => g_h1
    k_agg<<<NN, 128>>>(x, p_agg);
    k_gemm_dual<<<gemmGrid, 256>>>(p_agg, x, Wpr, Wpw, p_h1, 1);
    k_zerostats<<<1, HH>>>();
    k_bnstats<<<dim3(4, 64), 128>>>(p_h1);
    k_bnfin<<<1, HH>>>(gamma, beta);
    k_bnapply<<<apb, 256>>>(p_h1);

    float* cur = p_h1;
    float* nxt = p_h2;
    for (int l = 0; l < 3; ++l) {
        k_agg<<<NN, 128>>>(cur, p_agg);
        k_gemm_dual<<<gemmGrid, 256>>>(p_agg, cur,
                                       Wrel + (size_t)l * HH * HH,
                                       Wroot + (size_t)l * HH * HH, nxt, 1);
        k_zerostats<<<1, HH>>>();
        k_bnstats<<<dim3(4, 64), 128>>>(nxt);
        k_bnfin<<<1, HH>>>(gamma + (size_t)(l + 1) * HH, beta + (size_t)(l + 1) * HH);
        k_bnapply<<<apb, 256>>>(nxt);
        float* tmp = cur; cur = nxt; nxt = tmp;
    }

    // final conv + log_softmax
    k_agg<<<NN, 128>>>(cur, p_agg);
    k_final<<<NN, 320>>>(p_agg, cur, Wfr, Wfw, out);
}

// round 3
// speedup vs baseline: 1.6948x; 1.6948x over previous
#include <cuda_runtime.h>
#include <cuda_bf16.h>
#include <math.h>
#include <stdint.h>

#define NN 10000
#define NP 10112            // 79 * 128, padded node count for GEMM tiles
#define EE 160000
#define HH 512
#define CC 10
#define BN_EPS 1e-5f

// ---------------- device scratch (no allocations allowed) ----------------
__device__ float g_h1[NP * HH];
__device__ float g_h2[NP * HH];
__device__ float g_agg[NP * HH];
__device__ __nv_bfloat16 g_xh[NP * HH], g_xl[NP * HH];
__device__ __nv_bfloat16 g_hh[NP * HH], g_hl[NP * HH];
__device__ __nv_bfloat16 g_ah[NP * HH], g_al[NP * HH];
__device__ __nv_bfloat16 g_wh[8 * HH * HH], g_wl[8 * HH * HH];
__device__ float g_scale[NN];
__device__ int   g_degi[NN];
__device__ int   g_rowptr[NN + 1];
__device__ int   g_fill[NN];
__device__ int   g_esrc[EE];
__device__ float g_sum[HH];
__device__ float g_sq[HH];
__device__ float g_bnA[HH];
__device__ float g_bnB[HH];

// ---------------- PTX helpers ----------------
__device__ __forceinline__ uint32_t cvta_s(const void* p) {
    return (uint32_t)__cvta_generic_to_shared(p);
}
__device__ __forceinline__ void cpa16(uint32_t dst, const void* src) {
    asm volatile("cp.async.cg.shared.global [%0], [%1], 16;\n" :: "r"(dst), "l"(src));
}
__device__ __forceinline__ void ldm_x4(uint32_t& r0, uint32_t& r1, uint32_t& r2, uint32_t& r3, uint32_t addr) {
    asm volatile("ldmatrix.sync.aligned.m8n8.x4.shared.b16 {%0,%1,%2,%3}, [%4];\n"
                 : "=r"(r0), "=r"(r1), "=r"(r2), "=r"(r3) : "r"(addr));
}
// NON-transposed x2: W stored [n][k] (k contiguous) is already the .col B layout.
__device__ __forceinline__ void ldm_x2(uint32_t& r0, uint32_t& r1, uint32_t addr) {
    asm volatile("ldmatrix.sync.aligned.m8n8.x2.shared.b16 {%0,%1}, [%2];\n"
                 : "=r"(r0), "=r"(r1) : "r"(addr));
}
__device__ __forceinline__ void mma_bf16(float* d, uint32_t a0, uint32_t a1, uint32_t a2, uint32_t a3,
                                         uint32_t b0, uint32_t b1) {
    asm volatile("mma.sync.aligned.m16n8k16.row.col.f32.bf16.bf16.f32 "
                 "{%0,%1,%2,%3}, {%4,%5,%6,%7}, {%8,%9}, {%0,%1,%2,%3};\n"
                 : "+f"(d[0]), "+f"(d[1]), "+f"(d[2]), "+f"(d[3])
                 : "r"(a0), "r"(a1), "r"(a2), "r"(a3), "r"(b0), "r"(b1));
}

// ---------------- CSR build ----------------
__global__ void k_zerocsr() {
    int i = blockIdx.x * blockDim.x + threadIdx.x;
    if (i < NN) { g_degi[i] = 0; g_fill[i] = 0; }
}
__global__ void k_deg(const int* __restrict__ ei) {
    int e = blockIdx.x * blockDim.x + threadIdx.x;
    if (e < EE) atomicAdd(&g_degi[ei[EE + e]], 1);
}
__global__ void k_scan() {
    __shared__ int sh[1024];
    __shared__ int carry;
    int t = threadIdx.x;
    if (t == 0) carry = 0;
    __syncthreads();
    for (int base = 0; base < NN; base += 1024) {
        int i = base + t;
        int v = (i < NN) ? g_degi[i] : 0;
        sh[t] = v;
        __syncthreads();
        for (int off = 1; off < 1024; off <<= 1) {
            int tv = (t >= off) ? sh[t - off] : 0;
            __syncthreads();
            sh[t] += tv;
            __syncthreads();
        }
        if (i < NN) g_rowptr[i + 1] = carry + sh[t];
        __syncthreads();
        if (t == 0) carry += sh[1023];
        __syncthreads();
    }
    if (t == 0) g_rowptr[0] = 0;
}
__global__ void k_scale() {
    int i = blockIdx.x * blockDim.x + threadIdx.x;
    if (i < NN) {
        int d = g_degi[i];
        g_scale[i] = 1.0f / (float)(d > 0 ? d : 1);
    }
}
__global__ void k_fill(const int* __restrict__ ei) {
    int e = blockIdx.x * blockDim.x + threadIdx.x;
    if (e < EE) {
        int dst = ei[EE + e];
        int pos = g_rowptr[dst] + atomicAdd(&g_fill[dst], 1);
        g_esrc[pos] = ei[e];
    }
}

// ---------------- pad zeroing + splits ----------------
__global__ void k_zeropad() {
    int i = blockIdx.x * blockDim.x + threadIdx.x;
    const int total = (NP - NN) * HH;
    if (i < total) {
        int off = NN * HH + i;
        __nv_bfloat16 z = __float2bfloat16(0.0f);
        g_xh[off] = z; g_xl[off] = z;
        g_hh[off] = z; g_hl[off] = z;
        g_ah[off] = z; g_al[off] = z;
    }
}
__global__ void k_splitmat(const float* __restrict__ s, __nv_bfloat16* __restrict__ dh,
                           __nv_bfloat16* __restrict__ dl, int n) {
    int i = blockIdx.x * blockDim.x + threadIdx.x;
    if (i < n) {
        float v = s[i];
        __nv_bfloat16 h = __float2bfloat16(v);
        dh[i] = h;
        dl[i] = __float2bfloat16(v - __bfloat162float(h));
    }
}

// ---------------- mean aggregation (block per node, 128 thr, float4) ----------------
__global__ void k_agg2(const float* __restrict__ h,
                       __nv_bfloat16* __restrict__ oh, __nv_bfloat16* __restrict__ ol,
                       float* __restrict__ of) {
    int node = blockIdx.x;
    int t = threadIdx.x;                 // 0..127 -> 4 floats each
    int s = g_rowptr[node];
    int e = g_rowptr[node + 1];
    float ax = 0.f, ay = 0.f, az = 0.f, aw = 0.f;
    int j = s;
    for (; j + 1 < e; j += 2) {
        int s0 = g_esrc[j];
        int s1 = g_esrc[j + 1];
        float4 v0 = ((const float4*)(h + (size_t)s0 * HH))[t];
        float4 v1 = ((const float4*)(h + (size_t)s1 * HH))[t];
        ax += v0.x + v1.x; ay += v0.y + v1.y;
        az += v0.z + v1.z; aw += v0.w + v1.w;
    }
    if (j < e) {
        int s0 = g_esrc[j];
        float4 v0 = ((const float4*)(h + (size_t)s0 * HH))[t];
        ax += v0.x; ay += v0.y; az += v0.z; aw += v0.w;
    }
    float sc = g_scale[node];
    ax *= sc; ay *= sc; az *= sc; aw *= sc;
    if (of) {
        ((float4*)(of + (size_t)node * HH))[t] = make_float4(ax, ay, az, aw);
    }
    if (oh) {
        __nv_bfloat16 hx = __float2bfloat16(ax), hy = __float2bfloat16(ay);
        __nv_bfloat16 hz = __float2bfloat16(az), hw = __float2bfloat16(aw);
        __nv_bfloat16 lx = __float2bfloat16(ax - __bfloat162float(hx));
        __nv_bfloat16 ly = __float2bfloat16(ay - __bfloat162float(hy));
        __nv_bfloat16 lz = __float2bfloat16(az - __bfloat162float(hz));
        __nv_bfloat16 lw = __float2bfloat16(aw - __bfloat162float(hw));
        __nv_bfloat162* ph = (__nv_bfloat162*)(oh + (size_t)node * HH);
        __nv_bfloat162* pl = (__nv_bfloat162*)(ol + (size_t)node * HH);
        ph[t * 2 + 0] = __nv_bfloat162(hx, hy);
        ph[t * 2 + 1] = __nv_bfloat162(hz, hw);
        pl[t * 2 + 0] = __nv_bfloat162(lx, ly);
        pl[t * 2 + 1] = __nv_bfloat162(lz, lw);
    }
}

// ---------------- tensor-core dual GEMM (bf16 split, fp32 accum, relu) ----------------
// C(NP x 512) = A1 @ W1^T + A2 @ W2^T over K=512 each (K-concat = 1024).
// 128x64 CTA tile, 8 warps (4M x 2N), warp tile 32x32, k-step 16, cp.async double buffer.
#define LDS 24   // padded smem stride in halves

__global__ __launch_bounds__(256, 2)
void k_gemm3(const __nv_bfloat16* __restrict__ a1h, const __nv_bfloat16* __restrict__ a1l,
             const __nv_bfloat16* __restrict__ a2h, const __nv_bfloat16* __restrict__ a2l,
             const __nv_bfloat16* __restrict__ w1h, const __nv_bfloat16* __restrict__ w1l,
             const __nv_bfloat16* __restrict__ w2h, const __nv_bfloat16* __restrict__ w2l,
             float* __restrict__ C, int relu) {
    __shared__ __align__(16) __nv_bfloat16 sAh[2][128][LDS];
    __shared__ __align__(16) __nv_bfloat16 sAl[2][128][LDS];
    __shared__ __align__(16) __nv_bfloat16 sWh[2][64][LDS];
    __shared__ __align__(16) __nv_bfloat16 sWl[2][64][LDS];

    const int tx = threadIdx.x;
    const int lane = tx & 31;
    const int warp = tx >> 5;
    const int wm = (warp & 3) * 32;
    const int wn = (warp >> 2) * 32;
    const int m0 = blockIdx.y * 128;
    const int n0 = blockIdx.x * 64;

    const int lrow = tx >> 1;            // 0..127
    const int lseg = (tx & 1) * 8;       // half offset (16B)
    const int u = tx & 127;
    const int wrow = u >> 1;             // 0..63
    const int wseg = (u & 1) * 8;

    float acc[2][4][4];
#pragma unroll
    for (int i = 0; i < 2; i++)
#pragma unroll
        for (int j = 0; j < 4; j++)
#pragma unroll
            for (int q = 0; q < 4; q++) acc[i][j][q] = 0.f;

    const int NK = 64;   // 64 k16-steps (32 per operand pair)

    auto loadStage = [&](int kt, int st) {
        const __nv_bfloat16* Ah = (kt < 32) ? a1h : a2h;
        const __nv_bfloat16* Al = (kt < 32) ? a1l : a2l;
        const __nv_bfloat16* Wh = (kt < 32) ? w1h : w2h;
        const __nv_bfloat16* Wl = (kt < 32) ? w1l : w2l;
        int k0 = (kt & 31) * 16;
        cpa16(cvta_s(&sAh[st][lrow][lseg]), Ah + (size_t)(m0 + lrow) * HH + k0 + lseg);
        cpa16(cvta_s(&sAl[st][lrow][lseg]), Al + (size_t)(m0 + lrow) * HH + k0 + lseg);
        if (tx < 128)
            cpa16(cvta_s(&sWh[st][wrow][wseg]), Wh + (size_t)(n0 + wrow) * HH + k0 + wseg);
        else
            cpa16(cvta_s(&sWl[st][wrow][wseg]), Wl + (size_t)(n0 + wrow) * HH + k0 + wseg);
        asm volatile("cp.async.commit_group;\n");
    };

    loadStage(0, 0);

    for (int kt = 0; kt < NK; ++kt) {
        int st = kt & 1;
        if (kt + 1 < NK) {
            loadStage(kt + 1, st ^ 1);
            asm volatile("cp.async.wait_group 1;\n");
        } else {
            asm volatile("cp.async.wait_group 0;\n");
        }
        __syncthreads();

        uint32_t ah[2][4], al[2][4], bh[4][2], bl[4][2];
#pragma unroll
        for (int i = 0; i < 2; i++) {
            int r = wm + i * 16 + (lane & 15);
            int c = ((lane >> 4) & 1) * 8;
            ldm_x4(ah[i][0], ah[i][1], ah[i][2], ah[i][3], cvta_s(&sAh[st][r][c]));
            ldm_x4(al[i][0], al[i][1], al[i][2], al[i][3], cvta_s(&sAl[st][r][c]));
        }
#pragma unroll
        for (int j = 0; j < 4; j++) {
            int r = wn + j * 8 + (lane & 7);
            int c = ((lane >> 3) & 1) * 8;
            ldm_x2(bh[j][0], bh[j][1], cvta_s(&sWh[st][r][c]));
            ldm_x2(bl[j][0], bl[j][1], cvta_s(&sWl[st][r][c]));
        }
#pragma unroll
        for (int i = 0; i < 2; i++)
#pragma unroll
            for (int j = 0; j < 4; j++) {
                mma_bf16(acc[i][j], ah[i][0], ah[i][1], ah[i][2], ah[i][3], bh[j][0], bh[j][1]);
                mma_bf16(acc[i][j], ah[i][0], ah[i][1], ah[i][2], ah[i][3], bl[j][0], bl[j][1]);
                mma_bf16(acc[i][j], al[i][0], al[i][1], al[i][2], al[i][3], bh[j][0], bh[j][1]);
            }
        __syncthreads();
    }

    // epilogue: relu + store fp32
#pragma unroll
    for (int i = 0; i < 2; i++)
#pragma unroll
        for (int j = 0; j < 4; j++) {
            int r = m0 + wm + i * 16 + (lane >> 2);
            int c = n0 + wn + j * 8 + (lane & 3) * 2;
            float2 v0 = make_float2(acc[i][j][0], acc[i][j][1]);
            float2 v1 = make_float2(acc[i][j][2], acc[i][j][3]);
            if (relu) {
                v0.x = fmaxf(v0.x, 0.f); v0.y = fmaxf(v0.y, 0.f);
                v1.x = fmaxf(v1.x, 0.f); v1.y = fmaxf(v1.y, 0.f);
            }
            *(float2*)(C + (size_t)r * HH + c) = v0;
            *(float2*)(C + (size_t)(r + 8) * HH + c) = v1;
        }
}

// ---------------- BatchNorm ----------------
__global__ void k_zerostats() {
    int f = threadIdx.x;
    g_sum[f] = 0.f; g_sq[f] = 0.f;
}
__global__ void k_bnstats(const float* __restrict__ h) {
    int f = blockIdx.x * 128 + threadIdx.x;
    int r0 = blockIdx.y * 157;
    int r1 = r0 + 157; if (r1 > NN) r1 = NN;
    float s = 0.f, q = 0.f;
    for (int r = r0; r < r1; ++r) {
        float v = h[(size_t)r * HH + f];
        s += v; q += v * v;
    }
    atomicAdd(&g_sum[f], s);
    atomicAdd(&g_sq[f], q);
}
__global__ void k_bnfin(const float* __restrict__ gamma, const float* __restrict__ beta) {
    int f = threadIdx.x;
    float mu = g_sum[f] / (float)NN;
    float var = g_sq[f] / (float)NN - mu * mu;
    float inv = rsqrtf(var + BN_EPS);
    float sc = gamma[f] * inv;
    g_bnA[f] = sc;
    g_bnB[f] = beta[f] - mu * sc;
}
// BN apply + bf16 hi/lo split in one pass
__global__ void k_bnapply2(float* __restrict__ h,
                           __nv_bfloat16* __restrict__ hh, __nv_bfloat16* __restrict__ hl) {
    int idx = blockIdx.x * blockDim.x + threadIdx.x;   // over NN*HH/4
    if (idx >= NN * HH / 4) return;
    int f4 = idx & (HH / 4 - 1);
    float4 v = ((float4*)h)[idx];
    float4 a = ((const float4*)g_bnA)[f4];
    float4 b = ((const float4*)g_bnB)[f4];
    v.x = v.x * a.x + b.x;
    v.y = v.y * a.y + b.y;
    v.z = v.z * a.z + b.z;
    v.w = v.w * a.w + b.w;
    ((float4*)h)[idx] = v;
    __nv_bfloat16 hx = __float2bfloat16(v.x), hy = __float2bfloat16(v.y);
    __nv_bfloat16 hz = __float2bfloat16(v.z), hw = __float2bfloat16(v.w);
    __nv_bfloat16 lx = __float2bfloat16(v.x - __bfloat162float(hx));
    __nv_bfloat16 ly = __float2bfloat16(v.y - __bfloat162float(hy));
    __nv_bfloat16 lz = __float2bfloat16(v.z - __bfloat162float(hz));
    __nv_bfloat16 lw = __float2bfloat16(v.w - __bfloat162float(hw));
    ((__nv_bfloat162*)hh)[idx * 2 + 0] = __nv_bfloat162(hx, hy);
    ((__nv_bfloat162*)hh)[idx * 2 + 1] = __nv_bfloat162(hz, hw);
    ((__nv_bfloat162*)hl)[idx * 2 + 0] = __nv_bfloat162(lx, ly);
    ((__nv_bfloat162*)hl)[idx * 2 + 1] = __nv_bfloat162(lz, lw);
}

// ---------------- final conv (C=10) + log_softmax ----------------
__global__ __launch_bounds__(320)
void k_final(const float* __restrict__ agg, const float* __restrict__ h,
             const float* __restrict__ Wr, const float* __restrict__ Ww,
             float* __restrict__ out) {
    __shared__ float sa[HH];
    __shared__ float sh[HH];
    __shared__ float slog[CC];
    __shared__ float sLse;
    int node = blockIdx.x;
    int t = threadIdx.x;
    for (int i = t; i < HH; i += 320) {
        sa[i] = agg[(size_t)node * HH + i];
        sh[i] = h[(size_t)node * HH + i];
    }
    __syncthreads();
    int w = t >> 5, lane = t & 31;
    float s = 0.f;
    for (int k = lane; k < HH; k += 32)
        s += sa[k] * Wr[w * HH + k] + sh[k] * Ww[w * HH + k];
#pragma unroll
    for (int o = 16; o; o >>= 1) s += __shfl_down_sync(0xffffffff, s, o);
    if (lane == 0) slog[w] = s;
    __syncthreads();
    if (t == 0) {
        float mx = slog[0];
        for (int c = 1; c < CC; c++) mx = fmaxf(mx, slog[c]);
        float sum = 0.f;
        for (int c = 0; c < CC; c++) sum += expf(slog[c] - mx);
        sLse = mx + logf(sum);
    }
    __syncthreads();
    if (t < CC) out[(size_t)node * CC + t] = slog[t] - sLse;
}

// ---------------- launch ----------------
extern "C" void kernel_launch(void* const* d_in, const int* in_sizes, int n_in,
                              void* d_out, int out_size) {
    const float* x     = (const float*)d_in[0];
    const int*   ei    = (const int*)d_in[1];
    const float* Wpr   = (const float*)d_in[2];
    const float* Wpw   = (const float*)d_in[3];
    const float* Wrel  = (const float*)d_in[4];
    const float* Wroot = (const float*)d_in[5];
    const float* gamma = (const float*)d_in[6];
    const float* beta  = (const float*)d_in[7];
    const float* Wfr   = (const float*)d_in[8];
    const float* Wfw   = (const float*)d_in[9];
    float* out = (float*)d_out;

    static float *p_h1 = nullptr, *p_h2 = nullptr, *p_agg = nullptr;
    static __nv_bfloat16 *p_xh, *p_xl, *p_hh, *p_hl, *p_ah, *p_al, *p_wh, *p_wl;
    if (!p_h1) {
        cudaGetSymbolAddress((void**)&p_h1, g_h1);
        cudaGetSymbolAddress((void**)&p_h2, g_h2);
        cudaGetSymbolAddress((void**)&p_agg, g_agg);
        cudaGetSymbolAddress((void**)&p_xh, g_xh);
        cudaGetSymbolAddress((void**)&p_xl, g_xl);
        cudaGetSymbolAddress((void**)&p_hh, g_hh);
        cudaGetSymbolAddress((void**)&p_hl, g_hl);
        cudaGetSymbolAddress((void**)&p_ah, g_ah);
        cudaGetSymbolAddress((void**)&p_al, g_al);
        cudaGetSymbolAddress((void**)&p_wh, g_wh);
        cudaGetSymbolAddress((void**)&p_wl, g_wl);
    }

    const int MM = HH * HH;    // 262144 elems per weight matrix
    dim3 gemmGrid(HH / 64, NP / 128);   // (8, 79)
    int eb = (EE + 255) / 256;
    int nb = (NN + 255) / 256;
    int apb = (NN * HH / 4 + 255) / 256;
    int padb = ((NP - NN) * HH + 255) / 256;
    int mb1 = (MM + 255) / 256;
    int mb3 = (3 * MM + 255) / 256;
    int xb = (NN * HH + 255) / 256;

    // CSR build
    k_zerocsr<<<nb, 256>>>();
    k_deg<<<eb, 256>>>(ei);
    k_scan<<<1, 1024>>>();
    k_scale<<<nb, 256>>>();
    k_fill<<<eb, 256>>>(ei);

    // pads + input/weight splits
    k_zeropad<<<padb, 256>>>();
    k_splitmat<<<xb, 256>>>(x, p_xh, p_xl, NN * HH);
    k_splitmat<<<mb1, 256>>>(Wpr,   p_wh + 0 * MM, p_wl + 0 * MM, MM);
    k_splitmat<<<mb1, 256>>>(Wpw,   p_wh + 1 * MM, p_wl + 1 * MM, MM);
    k_splitmat<<<mb3, 256>>>(Wrel,  p_wh + 2 * MM, p_wl + 2 * MM, 3 * MM);
    k_splitmat<<<mb3, 256>>>(Wroot, p_wh + 5 * MM, p_wl + 5 * MM, 3 * MM);

    // proj layer: conv(x) -> relu -> bn -> split
    k_agg2<<<NN, 128>>>(x, p_ah, p_al, nullptr);
    k_gemm3<<<gemmGrid, 256>>>(p_ah, p_al, p_xh, p_xl,
                               p_wh + 0 * MM, p_wl + 0 * MM,
                               p_wh + 1 * MM, p_wl + 1 * MM, p_h1, 1);
    k_zerostats<<<1, HH>>>();
    k_bnstats<<<dim3(4, 64), 128>>>(p_h1);
    k_bnfin<<<1, HH>>>(gamma, beta);
    k_bnapply2<<<apb, 256>>>(p_h1, p_hh, p_hl);

    float* cur = p_h1;
    float* nxt = p_h2;
    for (int l = 0; l < 3; ++l) {
        k_agg2<<<NN, 128>>>(cur, p_ah, p_al, nullptr);
        k_gemm3<<<gemmGrid, 256>>>(p_ah, p_al, p_hh, p_hl,
                                   p_wh + (2 + l) * MM, p_wl + (2 + l) * MM,
                                   p_wh + (5 + l) * MM, p_wl + (5 + l) * MM, nxt, 1);
        k_zerostats<<<1, HH>>>();
        k_bnstats<<<dim3(4, 64), 128>>>(nxt);
        k_bnfin<<<1, HH>>>(gamma + (size_t)(l + 1) * HH, beta + (size_t)(l + 1) * HH);
        k_bnapply2<<<apb, 256>>>(nxt, p_hh, p_hl);
        float* tmp = cur; cur = nxt; nxt = tmp;
    }

    // final conv + log_softmax
    k_agg2<<<NN, 128>>>(cur, nullptr, nullptr, p_agg);
    k_final<<<NN, 320>>>(p_agg, cur, Wfr, Wfw, out);
}